// round 5
// baseline (speedup 1.0000x reference)
#include <cuda_runtime.h>
#include <cuda_bf16.h>
#include <cstdint>

#define D 128
#define NTOT ((1 << 18) - 1)      // 262143
#define LEAF0 ((1 << 17) - 1)     // 131071
#define LDK 136                    // padded row pitch (bf16 elems) -> conflict-free frags

__device__ float g_raw[NTOT * D];          // embed output (= ret for leaves)
__device__ float g_contrib[NTOT * D];      // per-child contribution (incl. edge bias)
__device__ float g_emb_small[1023 * D];    // emb for nodes 0..1022 (small levels)
__device__ int   g_bucket[8 * (NTOT - 1)];
__device__ int   g_count[17 * 8];
__device__ __align__(16) __nv_bfloat16 g_Wt[9 * 2 * D * LDK];  // W^T hi/lo per matrix
__device__ int      g_bar_count;
__device__ unsigned g_bar_gen;

// split x into hi(bf16) + lo(bf16 of residual); pack pairs (x,y): low16=x, high16=y
__device__ __forceinline__ void split_pair(float x, float y, uint32_t& h, uint32_t& l) {
    asm("cvt.rn.bf16x2.f32 %0, %1, %2;" : "=r"(h) : "f"(y), "f"(x));
    float hx = __uint_as_float(h << 16);
    float hy = __uint_as_float(h & 0xffff0000u);
    asm("cvt.rn.bf16x2.f32 %0, %1, %2;" : "=r"(l) : "f"(y - hy), "f"(x - hx));
}

__device__ __forceinline__ void mma16816(float c[4], uint32_t a0, uint32_t a1,
                                         uint32_t a2, uint32_t a3,
                                         uint32_t b0, uint32_t b1) {
    asm volatile(
        "mma.sync.aligned.m16n8k16.row.col.f32.bf16.bf16.f32 "
        "{%0,%1,%2,%3}, {%4,%5,%6,%7}, {%8,%9}, {%0,%1,%2,%3};\n"
        : "+f"(c[0]), "+f"(c[1]), "+f"(c[2]), "+f"(c[3])
        : "r"(a0), "r"(a1), "r"(a2), "r"(a3), "r"(b0), "r"(b1));
}

// ============================================================================
__global__ void zero_kernel() {
    int i = threadIdx.x;
    if (i < 17 * 8) g_count[i] = 0;
}

__global__ void bucket_kernel(const int* __restrict__ edges) {
    int c = blockIdx.x * blockDim.x + threadIdx.x + 2047;   // depth >= 11
    if (c >= NTOT) return;
    int d   = 31 - __clz(c + 1);
    int lev = d - 1;                    // parent level 10..16
    int M    = 1 << d;
    int base = 8 * (M - 2);
    int e = edges[c];
    int slot = atomicAdd(&g_count[lev * 8 + e], 1);
    g_bucket[base + e * M + slot] = c;
}

// W^T layout: Wt[n][k] (n rows, k cols, pitch LDK), hi then lo plane.
__global__ void prep_B_kernel(const float* __restrict__ data_W,
                              const float* __restrict__ edge_W) {
    int m = blockIdx.x;                 // 0..7 edges, 8 = data_W
    const float* W = (m == 8) ? data_W : (edge_W + (size_t)m * D * D);
    __nv_bfloat16* dst = g_Wt + (size_t)m * 2 * D * LDK;
    for (int idx = threadIdx.x; idx < D * D; idx += blockDim.x) {
        int k = idx >> 7, n = idx & 127;
        float v = W[idx];
        __nv_bfloat16 h = __float2bfloat16(v);
        float hv = __bfloat162float(h);
        __nv_bfloat16 l = __float2bfloat16(v - hv);
        dst[n * LDK + k] = h;
        dst[D * LDK + n * LDK + k] = l;
    }
}

// ---------------------------------------------------------------------------
// mma.sync GEMM. Tile = 128 rows x 128 cols, K=128, split-bf16 (3 terms).
// mode: 0 = embed (A = data_vecs[data[j]], out = g_raw, bias = data_b)
//       1 = leaf children (A = raw[list[j]], out = g_contrib, bias = edge_b[e])
//       2 = internal children (A = relu((raw+c1+c2)/3), out = g_contrib)
// 512 threads: warp w -> rows (w&7)*16..+15, col half (w>>3)*64..+63.
// ---------------------------------------------------------------------------
#define SM_WH   0
#define SM_AH   69632
#define SM_BIAS 139264
#define SM_IDS  139776
#define SM_TOT  140288

__global__ void __launch_bounds__(512, 1)
mma_gemm_kernel(const int* __restrict__ data,
                const float* __restrict__ data_vecs,
                const int* __restrict__ counts, int bucket_base, int Mlist,
                const float* __restrict__ bias_all,
                int mode, int nb)
{
    extern __shared__ unsigned char smem[];
    __nv_bfloat16* Wh = (__nv_bfloat16*)(smem + SM_WH);        // hi + lo planes
    __nv_bfloat16* Ah = (__nv_bfloat16*)(smem + SM_AH);        // hi + lo planes
    float* bias_sm = (float*)(smem + SM_BIAS);
    int*   ids_sm  = (int*)(smem + SM_IDS);

    const int tid = threadIdx.x;
    const int e  = (mode == 0) ? 8 : (blockIdx.x / nb);
    const int bi = (mode == 0) ? blockIdx.x : (blockIdx.x % nb);
    const int count = (mode == 0) ? NTOT : counts[e];
    if (count == 0) return;

    // Stage W^T hi/lo (69632 B)
    {
        const uint4* src = (const uint4*)(g_Wt + (size_t)e * 2 * D * LDK);
        uint4* dst = (uint4*)Wh;
        for (int i = tid; i < 4352; i += 512) dst[i] = src[i];
    }
    {
        const float* bias = (mode == 0) ? bias_all : (bias_all + e * D);
        if (tid < D) bias_sm[tid] = bias[tid];
    }
    __syncthreads();

    const int lane = tid & 31;
    const int warp = tid >> 5;
    const int g  = lane >> 2;
    const int t2 = (lane & 3) * 2;
    const int m0 = (warp & 7) * 16;
    const int nbase = (warp >> 3) * 64;

    const int* list = g_bucket + bucket_base + (size_t)e * Mlist;
    float* outbase = (mode == 0) ? g_raw : g_contrib;

    // frag base pointers (elem units)
    const __nv_bfloat16* AhR0 = Ah + (m0 + g) * LDK + t2;            // hi plane
    const __nv_bfloat16* AhR1 = Ah + (m0 + g + 8) * LDK + t2;
    const __nv_bfloat16* AlR0 = AhR0 + D * LDK;
    const __nv_bfloat16* AlR1 = AhR1 + D * LDK;
    const __nv_bfloat16* WhG  = Wh + (nbase + g) * LDK + t2;
    const __nv_bfloat16* WlG  = WhG + D * LDK;

    const int ntiles = (count + 127) >> 7;
    const int r  = tid >> 2;         // staging row 0..127
    const int cq = tid & 3;          // staging col quarter

    for (int tile = bi; tile < ntiles; tile += nb) {
        // ---------------- stage A (convert to hi/lo bf16) ----------------
        {
            int j = tile * 128 + r;
            int jj = min(j, count - 1);
            int id;
            const float4 *s0 = nullptr, *s1 = nullptr, *s2 = nullptr;
            if (mode == 0) {
                id = jj;
                s0 = (const float4*)(data_vecs + (size_t)__ldg(&data[jj]) * D);
            } else {
                id = list[jj];
                s0 = (const float4*)(g_raw + (size_t)id * D);
                if (mode == 2) {
                    s1 = (const float4*)(g_contrib + (size_t)(2 * id + 1) * D);
                    s2 = (const float4*)(g_contrib + (size_t)(2 * id + 2) * D);
                }
            }
            if (cq == 0) ids_sm[r] = id;
            #pragma unroll
            for (int i = 0; i < 8; ++i) {
                int c = cq * 32 + i * 4;
                float4 v = s0[c >> 2];
                if (mode == 2) {
                    float4 a = s1[c >> 2], b = s2[c >> 2];
                    v.x = fmaxf((v.x + a.x + b.x) * (1.f / 3.f), 0.f);
                    v.y = fmaxf((v.y + a.y + b.y) * (1.f / 3.f), 0.f);
                    v.z = fmaxf((v.z + a.z + b.z) * (1.f / 3.f), 0.f);
                    v.w = fmaxf((v.w + a.w + b.w) * (1.f / 3.f), 0.f);
                }
                uint32_t h0, l0, h1, l1;
                split_pair(v.x, v.y, h0, l0);
                split_pair(v.z, v.w, h1, l1);
                *(uint2*)(Ah + r * LDK + c) = make_uint2(h0, h1);
                *(uint2*)(Ah + D * LDK + r * LDK + c) = make_uint2(l0, l1);
            }
        }
        __syncthreads();

        // ---------------- MMA main loop ----------------
        float acc[8][4];
        #pragma unroll
        for (int nt = 0; nt < 8; ++nt)
            { acc[nt][0] = 0.f; acc[nt][1] = 0.f; acc[nt][2] = 0.f; acc[nt][3] = 0.f; }

        #pragma unroll
        for (int ks = 0; ks < 8; ++ks) {
            const int k0 = ks * 16;
            uint32_t ah0 = *(const uint32_t*)(AhR0 + k0);
            uint32_t ah1 = *(const uint32_t*)(AhR1 + k0);
            uint32_t ah2 = *(const uint32_t*)(AhR0 + k0 + 8);
            uint32_t ah3 = *(const uint32_t*)(AhR1 + k0 + 8);
            uint32_t al0 = *(const uint32_t*)(AlR0 + k0);
            uint32_t al1 = *(const uint32_t*)(AlR1 + k0);
            uint32_t al2 = *(const uint32_t*)(AlR0 + k0 + 8);
            uint32_t al3 = *(const uint32_t*)(AlR1 + k0 + 8);
            #pragma unroll
            for (int nt = 0; nt < 8; ++nt) {
                const __nv_bfloat16* wp = WhG + nt * 8 * LDK + k0;
                uint32_t bh0 = *(const uint32_t*)(wp);
                uint32_t bh1 = *(const uint32_t*)(wp + 8);
                const __nv_bfloat16* wq = WlG + nt * 8 * LDK + k0;
                uint32_t bl0 = *(const uint32_t*)(wq);
                uint32_t bl1 = *(const uint32_t*)(wq + 8);
                mma16816(acc[nt], ah0, ah1, ah2, ah3, bh0, bh1);   // hi*Whi
                mma16816(acc[nt], al0, al1, al2, al3, bh0, bh1);   // lo*Whi
                mma16816(acc[nt], ah0, ah1, ah2, ah3, bl0, bl1);   // hi*Wlo
            }
        }

        // ---------------- epilogue ----------------
        {
            int r0 = ids_sm[m0 + g];
            int r1 = ids_sm[m0 + g + 8];
            float* o0 = outbase + (size_t)r0 * D;
            float* o1 = outbase + (size_t)r1 * D;
            #pragma unroll
            for (int nt = 0; nt < 8; ++nt) {
                int n0 = nbase + nt * 8 + t2;
                float b0 = bias_sm[n0], b1 = bias_sm[n0 + 1];
                *(float2*)(o0 + n0) = make_float2(acc[nt][0] + b0, acc[nt][1] + b1);
                *(float2*)(o1 + n0) = make_float2(acc[nt][2] + b0, acc[nt][3] + b1);
            }
        }
        __syncthreads();
    }
}

// ---------------------------------------------------------------------------
// Fused small levels (l = 9..0) with software grid barrier. 128 blocks x 128 thr.
// ---------------------------------------------------------------------------
#define NBL 128
__device__ __forceinline__ void grid_bar() {
    __syncthreads();
    if (threadIdx.x == 0) {
        unsigned gen = *((volatile unsigned*)&g_bar_gen);
        __threadfence();
        if (atomicAdd(&g_bar_count, 1) == NBL - 1) {
            g_bar_count = 0;
            __threadfence();
            atomicAdd(&g_bar_gen, 1u);
        } else {
            while (*((volatile unsigned*)&g_bar_gen) == gen) { }
        }
        __threadfence();
    }
    __syncthreads();
}

__global__ void small_levels_kernel(const int* __restrict__ edges,
                                    const float* __restrict__ edge_W,
                                    const float* __restrict__ edge_b)
{
    __shared__ float v1[D], v2[D];
    const int tid = threadIdx.x;
    for (int l = 9; l >= 0; --l) {
        const int npar = 1 << l, p0 = npar - 1;
        for (int p = p0 + blockIdx.x; p < p0 + npar; p += NBL) {
            const int c1 = 2 * p + 1, c2 = 2 * p + 2;
            float r1, r2;
            if (l == 9) {   // children are level-10 parents: emb from raw+contrib
                r1 = fmaxf((g_raw[(size_t)c1 * D + tid]
                            + g_contrib[(size_t)(2 * c1 + 1) * D + tid]
                            + g_contrib[(size_t)(2 * c1 + 2) * D + tid]) * (1.f / 3.f), 0.f);
                r2 = fmaxf((g_raw[(size_t)c2 * D + tid]
                            + g_contrib[(size_t)(2 * c2 + 1) * D + tid]
                            + g_contrib[(size_t)(2 * c2 + 2) * D + tid]) * (1.f / 3.f), 0.f);
            } else {
                r1 = fmaxf(g_emb_small[(size_t)c1 * D + tid], 0.f);
                r2 = fmaxf(g_emb_small[(size_t)c2 * D + tid], 0.f);
            }
            v1[tid] = r1; v2[tid] = r2;
            const int e1 = edges[c1], e2 = edges[c2];
            __syncthreads();
            const float* W1 = edge_W + (size_t)e1 * D * D + tid;
            const float* W2 = edge_W + (size_t)e2 * D * D + tid;
            float acc = edge_b[e1 * D + tid] + edge_b[e2 * D + tid];
            #pragma unroll 8
            for (int k = 0; k < D; ++k)
                acc += v1[k] * W1[k * D] + v2[k] * W2[k * D];
            float h = (g_raw[(size_t)p * D + tid] + acc) * (1.f / 3.f);
            g_emb_small[(size_t)p * D + tid] = h;
            __syncthreads();
        }
        grid_bar();
    }
}

// ---------------------------------------------------------------------------
// Scores. emb: node<1023 -> g_emb_small; internal -> (raw+c1+c2)/3; leaf -> raw.
// ---------------------------------------------------------------------------
__global__ void score_kernel(const float* __restrict__ score_W,
                             float* __restrict__ out)
{
    __shared__ float sW[D];
    const int tid = threadIdx.x;
    if (tid < D) sW[tid] = score_W[tid];
    __syncthreads();
    const int w = tid >> 5, lane = tid & 31;
    const float4 s4 = ((const float4*)sW)[lane];
    const int gw = blockIdx.x * 8 + w;
    const int nw = gridDim.x * 8;
    for (int node = gw; node < NTOT; node += nw) {
        float4 v;
        if (node >= LEAF0) {
            v = ((const float4*)(g_raw + (size_t)node * D))[lane];
        } else if (node >= 1023) {
            float4 r  = ((const float4*)(g_raw     + (size_t)node * D))[lane];
            float4 a  = ((const float4*)(g_contrib + (size_t)(2 * node + 1) * D))[lane];
            float4 b  = ((const float4*)(g_contrib + (size_t)(2 * node + 2) * D))[lane];
            v = make_float4((r.x + a.x + b.x) * (1.f / 3.f),
                            (r.y + a.y + b.y) * (1.f / 3.f),
                            (r.z + a.z + b.z) * (1.f / 3.f),
                            (r.w + a.w + b.w) * (1.f / 3.f));
        } else {
            v = ((const float4*)(g_emb_small + (size_t)node * D))[lane];
        }
        float d = v.x * s4.x + v.y * s4.y + v.z * s4.z + v.w * s4.w;
        #pragma unroll
        for (int off = 16; off; off >>= 1)
            d += __shfl_xor_sync(0xffffffffu, d, off);
        if (lane == 0) out[node] = d;
    }
}

extern "C" void kernel_launch(void* const* d_in, const int* in_sizes, int n_in,
                              void* d_out, int out_size)
{
    const int*   data      = (const int*)  d_in[0];
    const int*   edges     = (const int*)  d_in[1];
    const float* data_vecs = (const float*)d_in[2];
    const float* data_W    = (const float*)d_in[3];
    const float* data_b    = (const float*)d_in[4];
    const float* edge_W    = (const float*)d_in[5];
    const float* edge_b    = (const float*)d_in[6];
    const float* score_W   = (const float*)d_in[7];
    float* out = (float*)d_out;
    (void)in_sizes; (void)n_in; (void)out_size;

    cudaFuncSetAttribute(mma_gemm_kernel,
                         cudaFuncAttributeMaxDynamicSharedMemorySize, SM_TOT);

    int* d_count;
    cudaGetSymbolAddress((void**)&d_count, g_count);

    zero_kernel<<<1, 160>>>();
    bucket_kernel<<<(NTOT - 2047 + 255) / 256, 256>>>(edges);
    prep_B_kernel<<<9, 256>>>(data_W, edge_W);

    // Embed on tensor cores (mode 0)
    mma_gemm_kernel<<<148, 512, SM_TOT>>>(data, data_vecs,
                                          nullptr, 0, 0,
                                          data_b, 0, 148);

    // Large levels: l = 16 .. 10
    for (int l = 16; l >= 10; --l) {
        int dd = l + 1;
        int M2 = 1 << dd;                 // children at this level
        int base = 8 * (M2 - 2);
        int rows_pe = M2 >> 3;
        int nb = (rows_pe + 127) >> 7;
        if (nb < 1) nb = 1;
        if (nb > 18) nb = 18;
        mma_gemm_kernel<<<8 * nb, 512, SM_TOT>>>(nullptr, nullptr,
                                                 d_count + l * 8, base, M2,
                                                 edge_b, (l == 16) ? 1 : 2, nb);
    }

    // Small levels fused (l = 9..0)
    small_levels_kernel<<<NBL, 128>>>(edges, edge_W, edge_b);

    score_kernel<<<592, 256>>>(score_W, out);
}